// round 16
// baseline (speedup 1.0000x reference)
#include <cuda_runtime.h>
#include <cuda_fp16.h>
#include <float.h>
#include <math.h>
#include <cstdint>

#define BATCH 8
#define CH    64
#define NPT   4096
#define OUTC  64
#define KNN   20
#define CK    58          // channels 6..63 used for knn
#define SKIP  6
#define NEG   0.2f
#define KPAD  64          // padded K for MMA

typedef unsigned long long ull;

// ---------------- f32x2 packed math helpers (k_proj) ------------------------
__device__ __forceinline__ ull ffma2(ull a, ull b, ull c) {
    ull d; asm("fma.rn.f32x2 %0, %1, %2, %3;" : "=l"(d) : "l"(a), "l"(b), "l"(c)); return d;
}
__device__ __forceinline__ ull pack2(float lo, float hi) {
    ull r; asm("mov.b64 %0, {%1, %2};" : "=l"(r) : "f"(lo), "f"(hi)); return r;
}
__device__ __forceinline__ void unpack2(ull v, float &lo, float &hi) {
    asm("mov.b64 {%0, %1}, %2;" : "=f"(lo), "=f"(hi) : "l"(v));
}

// ---------------- warp MMA / async helpers (portable sm_80+ PTX) ------------
__device__ __forceinline__ uint32_t smem_u32(const void* p) {
    uint32_t a;
    asm("{ .reg .u64 t; cvta.to.shared.u64 t, %1; cvt.u32.u64 %0, t; }" : "=r"(a) : "l"(p));
    return a;
}
#define LDMX4(d0,d1,d2,d3,addr) \
    asm volatile("ldmatrix.sync.aligned.m8n8.x4.shared.b16 {%0,%1,%2,%3}, [%4];" \
        : "=r"(d0), "=r"(d1), "=r"(d2), "=r"(d3) : "r"(addr))
#define MMA16816(d,a0,a1,a2,a3,b0,b1) \
    asm volatile("mma.sync.aligned.m16n8k16.row.col.f32.f16.f16.f32 " \
        "{%0,%1,%2,%3},{%4,%5,%6,%7},{%8,%9},{%0,%1,%2,%3};" \
        : "+f"((d)[0]), "+f"((d)[1]), "+f"((d)[2]), "+f"((d)[3]) \
        : "r"(a0), "r"(a1), "r"(a2), "r"(a3), "r"(b0), "r"(b1))
#define CPASYNC16(smem_addr, gptr) \
    asm volatile("cp.async.cg.shared.global [%0], [%1], 16;" :: "r"(smem_addr), "l"(gptr))
#define CPASYNC4(smem_addr, gptr) \
    asm volatile("cp.async.ca.shared.global [%0], [%1], 4;" :: "r"(smem_addr), "l"(gptr))
#define CPASYNC_MBAR_ARRIVE(mbar) \
    asm volatile("cp.async.mbarrier.arrive.noinc.shared.b64 [%0];" :: "r"((uint32_t)(mbar)) : "memory")
#define MBARRIER_INIT(mb, c) \
    asm volatile("mbarrier.init.shared.b64 [%0], %1;" :: "r"((uint32_t)(mb)), "r"((uint32_t)(c)) : "memory")
#define MBARRIER_ARRIVE(mb) \
    asm volatile("mbarrier.arrive.shared.b64 _, [%0];" :: "r"((uint32_t)(mb)) : "memory")
#define MBARRIER_WAIT_PARITY(mb, par) do { \
    uint32_t _mb = (uint32_t)(mb), _p = (uint32_t)(par), _done; \
    asm volatile("{\n\t.reg .pred p;\n\t" \
        "mbarrier.try_wait.parity.acquire.cta.shared::cta.b64 p, [%1], %2;\n\t" \
        "selp.b32 %0, 1, 0, p;\n\t}" : "=r"(_done) : "r"(_mb), "r"(_p) : "memory"); \
    if (!_done) { \
        asm volatile("{\n\t.reg .pred P1;\n\t" \
            "WAIT_LOOP_%=:\n\t" \
            "mbarrier.try_wait.parity.acquire.cta.shared::cta.b64 P1, [%0], %1, 0x989680;\n\t" \
            "@P1 bra.uni WAIT_DONE_%=;\n\t" \
            "bra.uni WAIT_LOOP_%=;\n\t" \
            "WAIT_DONE_%=:\n\t}" :: "r"(_mb), "r"(_p) : "memory"); \
    } \
} while (0)

// ---------------- order-preserving float->u32 map ---------------------------
__device__ __forceinline__ uint32_t fmono(float f) {
    uint32_t u = __float_as_uint(f);
    return u ^ ((uint32_t)((int32_t)u >> 31) | 0x80000000u);
}
__device__ __forceinline__ float finv(uint32_t m) {
    uint32_t b = (m & 0x80000000u) ? (m ^ 0x80000000u) : ~m;
    return __uint_as_float(b);
}
__device__ __forceinline__ ull mkkey(float v, int j) {
    return ((ull)fmono(v) << 32) | (ull)(0xFFFFFFFFu - (uint32_t)j);
}

// ---------------- device scratch (static globals: allocation-free) ----------
__device__ unsigned short g_xhi[BATCH*NPT*KPAD];   // fp16 hi, [b][n][k]
__device__ unsigned short g_xlo[BATCH*NPT*KPAD];   // fp16 lo
__device__ float  g_sq  [BATCH*NPT];
__device__ int    g_idx [BATCH*NPT*KNN];
__device__ float  g_u   [BATCH*NPT*OUTC];
__device__ float  g_v   [BATCH*NPT*OUTC];
__device__ float  g_umax[BATCH*NPT*OUTC];
__device__ float  g_umin[BATCH*NPT*OUTC];
__device__ double g_S1  [OUTC];
__device__ double g_S2  [OUTC];
__device__ float  g_ab  [2*OUTC];

// ---------------- init ------------------------------------------------------
__global__ void k_init() {
    int o = threadIdx.x;
    g_S1[o] = 0.0; g_S2[o] = 0.0;
}

// ---------------- split: fp16 hi/lo transpose + squared norms ---------------
__global__ void k_split(const float* __restrict__ x) {
    int b = blockIdx.y;
    int n = blockIdx.x * 256 + threadIdx.x;
    size_t ro = ((size_t)b * NPT + n) * KPAD;
    __half2* xh = (__half2*)(g_xhi + ro);
    __half2* xl = (__half2*)(g_xlo + ro);
    float s = 0.f;
    #pragma unroll
    for (int k = 0; k < KPAD; k += 2) {
        float v0 = (k     < CK) ? x[((size_t)b * CH + SKIP + k    ) * NPT + n] : 0.f;
        float v1 = (k + 1 < CK) ? x[((size_t)b * CH + SKIP + k + 1) * NPT + n] : 0.f;
        s = fmaf(v0, v0, fmaf(v1, v1, s));
        __half h0 = __float2half(v0), h1 = __float2half(v1);
        __half l0 = __float2half(v0 - __half2float(h0));
        __half l1 = __float2half(v1 - __half2float(h1));
        xh[k >> 1] = __halves2half2(h0, h1);
        xl[k >> 1] = __halves2half2(l0, l1);
    }
    g_sq[b * NPT + n] = s;
}

// ---------------- fused KNN: HMMA GEMM + mbarrier ring + warp top-20 --------
#define TI 128
#define TJ 64
#define NTILES (NPT / TJ)
#define CAP 16
#define PITCHB 144        // 72 halfs per row, conflict-free for ldmatrix

// Ring of 4 B buffers (hi 9216 + lo 9216 = 18432 each).
// Buffers 2,3 overlay the A-tile staging region (A lives in regs after init).
#define OFF_B01   36864
#define OFF_SQI   (OFF_B01 + 2 * 18432)              // 73728
#define OFF_SQJ   (OFF_SQI + TI * 4)                 // 74240 (4 * TJ floats)
#define OFF_LIST  (OFF_SQJ + 4 * TJ * 4)             // 75264
#define OFF_CB    (OFF_LIST + TI * KNN * 8)          // 95744
#define OFF_CNT   (OFF_CB + TI * CAP * 8)            // 112128
#define OFF_MBAR  (OFF_CNT + TI * 4)                 // 112640 (full[4], empty[4])
#define KNN_SMEM_TOTAL (OFF_MBAR + 64)               // 112704

__global__ __launch_bounds__(256, 2) void k_knn() {
    extern __shared__ __align__(16) char smem[];
    const uint32_t sb = smem_u32(smem);
    const int tid = threadIdx.x;
    const int wid = tid >> 5, lane = tid & 31;
    const int pairid = wid >> 1;         // 0..3: warp pair for production
    const int ptid = tid & 63;           // thread index within pair
    const int b = blockIdx.y;
    const int i0 = blockIdx.x * TI;
    const int d0 = blockIdx.x * 2;       // first diagonal j-tile

    float* sqi_s = (float*)(smem + OFF_SQI);
    float* sqj_s = (float*)(smem + OFF_SQJ);
    ull*   list  = (ull*)(smem + OFF_LIST);
    ull*   cb    = (ull*)(smem + OFF_CB);
    int*   cnt   = (int*)(smem + OFF_CNT);
    const uint32_t mb_full  = sb + OFF_MBAR;        // [4] x 8B, 64 arrivals
    const uint32_t mb_empty = sb + OFF_MBAR + 32;   // [4] x 8B, 8 arrivals

    const uint32_t BUFB[4] = {OFF_B01, OFF_B01 + 18432, 0u, 18432u};

    const int rw = 16 * wid;
    const int ra = rw + (lane >> 2);
    const int rb = ra + 8;

    const int aRow = rw + (lane & 7) + ((lane >> 3) & 1) * 8;
    const int aKB  = ((lane >> 4) & 1) * 16;
    const uint32_t aHI = sb + 0     + aRow * PITCHB + aKB;
    const uint32_t aLO = sb + 18432 + aRow * PITCHB + aKB;
    const int bRow = (lane & 7) + ((lane >> 4) & 1) * 8;
    const int bKB  = ((lane >> 3) & 1) * 16;

    #define TILE_OF(t) ((t) == 0 ? d0 : ((t) == 1 ? d0 + 1 : \
                        (((t) - 2 >= d0) ? (t) : (t) - 2)))

    // pair-scoped produce of tile T into buffer bfq (64 threads, 16 quads each)
    #define PRODUCE(T, bfq) do { \
        const int _jn = TILE_OF(T) * TJ; \
        const uint32_t _bh = sb + BUFB[bfq]; \
        _Pragma("unroll") \
        for (int _k = 0; _k < 8; _k++) { \
            int _q = ptid + _k * 64; \
            int _r = _q >> 3, _c = _q & 7; \
            CPASYNC16(_bh + _r * PITCHB + _c * 16, \
                      g_xhi + ((size_t)b * NPT + _jn + _r) * KPAD + _c * 8); \
            CPASYNC16(_bh + 9216 + _r * PITCHB + _c * 16, \
                      g_xlo + ((size_t)b * NPT + _jn + _r) * KPAD + _c * 8); \
        } \
        CPASYNC4(sb + OFF_SQJ + ((bfq) * TJ + ptid) * 4, g_sq + b * NPT + _jn + ptid); \
        CPASYNC_MBAR_ARRIVE(mb_full + (bfq) * 8); \
    } while (0)

    // ---- mbarrier init, then sync before any arrive
    if (tid == 0) {
        #pragma unroll
        for (int q = 0; q < 4; q++) {
            MBARRIER_INIT(mb_full + q * 8, 64);
            MBARRIER_INIT(mb_empty + q * 8, 8);
        }
    }
    __syncthreads();

    // ---- prologue: pair 0 produces tile 0, pair 1 produces tile 1
    if (pairid == 0) PRODUCE(0, 0);
    if (pairid == 1) PRODUCE(1, 1);

    // ---- A staging (regular stores) + lists init
    const ull WORSTKEY = mkkey(-FLT_MAX, 0x7FFFFFFF);
    for (int l = tid; l < TI * KNN; l += 256) list[l] = WORSTKEY;
    if (tid < TI) { cnt[tid] = 0; sqi_s[tid] = g_sq[b * NPT + i0 + tid]; }
    for (int l = tid; l < TI * 8; l += 256) {
        int r = l >> 3, ch = l & 7;
        *(uint4*)(smem + 0     + r * PITCHB + ch * 16) =
            *(const uint4*)(g_xhi + ((size_t)b * NPT + i0 + r) * KPAD + ch * 8);
        *(uint4*)(smem + 18432 + r * PITCHB + ch * 16) =
            *(const uint4*)(g_xlo + ((size_t)b * NPT + i0 + r) * KPAD + ch * 8);
    }
    __syncthreads();

    // ---- A fragments to registers (A smem region becomes buffers 2,3 after)
    uint32_t Ah[4][4], Al[4][4];
    #pragma unroll
    for (int ks = 0; ks < 4; ks++) {
        LDMX4(Ah[ks][0], Ah[ks][1], Ah[ks][2], Ah[ks][3], aHI + ks * 32);
        LDMX4(Al[ks][0], Al[ks][1], Al[ks][2], Al[ks][3], aLO + ks * 32);
    }
    __syncthreads();   // all A reads done before buffers 2,3 get overwritten

    for (int tt = 0; tt < NTILES; tt++) {
        const int bf = tt & 3;
        const int jt = TILE_OF(tt) * TJ;

        // ---- pair (T2&3) produces tile tt+2 into buffer (tt+2)&3
        const int T2 = tt + 2;
        if (T2 < NTILES && pairid == (T2 & 3)) {
            const int b2 = T2 & 3;
            MBARRIER_WAIT_PARITY(mb_empty + b2 * 8, ((T2 >> 2) & 1) ^ 1);
            PRODUCE(T2, b2);
        }

        // ---- consume: wait buffer full
        MBARRIER_WAIT_PARITY(mb_full + bf * 8, (tt >> 2) & 1);

        float acc[8][4];
        #pragma unroll
        for (int t = 0; t < 8; t++)
            #pragma unroll
            for (int v = 0; v < 4; v++) acc[t][v] = 0.f;

        const uint32_t bhB = sb + BUFB[bf] + bRow * PITCHB + bKB;
        const uint32_t blB = bhB + 9216;

        #pragma unroll
        for (int ks = 0; ks < 4; ks++) {
            uint32_t bh[4][4];
            #pragma unroll
            for (int p = 0; p < 4; p++)
                LDMX4(bh[p][0], bh[p][1], bh[p][2], bh[p][3],
                      bhB + (16 * p) * PITCHB + ks * 32);
            uint32_t bl0[4], bl1[4];
            LDMX4(bl0[0], bl0[1], bl0[2], bl0[3], blB + ks * 32);
            LDMX4(bl1[0], bl1[1], bl1[2], bl1[3], blB + 16 * PITCHB + ks * 32);
            #pragma unroll
            for (int p = 0; p < 4; p++) {       // hi*hi
                MMA16816(acc[2 * p],     Ah[ks][0], Ah[ks][1], Ah[ks][2], Ah[ks][3], bh[p][0], bh[p][1]);
                MMA16816(acc[2 * p + 1], Ah[ks][0], Ah[ks][1], Ah[ks][2], Ah[ks][3], bh[p][2], bh[p][3]);
            }
            #pragma unroll
            for (int p = 0; p < 4; p++) {       // lo*hi (reuse bh)
                MMA16816(acc[2 * p],     Al[ks][0], Al[ks][1], Al[ks][2], Al[ks][3], bh[p][0], bh[p][1]);
                MMA16816(acc[2 * p + 1], Al[ks][0], Al[ks][1], Al[ks][2], Al[ks][3], bh[p][2], bh[p][3]);
            }
            // hi*lo: first two N-tiles from pre-loaded bl0/bl1, last two fresh
            MMA16816(acc[0], Ah[ks][0], Ah[ks][1], Ah[ks][2], Ah[ks][3], bl0[0], bl0[1]);
            MMA16816(acc[1], Ah[ks][0], Ah[ks][1], Ah[ks][2], Ah[ks][3], bl0[2], bl0[3]);
            MMA16816(acc[2], Ah[ks][0], Ah[ks][1], Ah[ks][2], Ah[ks][3], bl1[0], bl1[1]);
            MMA16816(acc[3], Ah[ks][0], Ah[ks][1], Ah[ks][2], Ah[ks][3], bl1[2], bl1[3]);
            #pragma unroll
            for (int p = 2; p < 4; p++) {
                uint32_t c0, c1, c2, c3;
                LDMX4(c0, c1, c2, c3, blB + (16 * p) * PITCHB + ks * 32);
                MMA16816(acc[2 * p],     Ah[ks][0], Ah[ks][1], Ah[ks][2], Ah[ks][3], c0, c1);
                MMA16816(acc[2 * p + 1], Ah[ks][0], Ah[ks][1], Ah[ks][2], Ah[ks][3], c2, c3);
            }
        }

        // ---- epilogue: pd = 2*inner - si - sj
        const float sia = sqi_s[ra], sib = sqi_s[rb];
        const int cbase = 2 * (lane & 3);
        #pragma unroll
        for (int t = 0; t < 8; t++) {
            float2 sj = *(const float2*)&sqj_s[bf * TJ + 8 * t + cbase];
            acc[t][0] = fmaf(2.f, acc[t][0], -(sia + sj.x));
            acc[t][1] = fmaf(2.f, acc[t][1], -(sia + sj.y));
            acc[t][2] = fmaf(2.f, acc[t][2], -(sib + sj.x));
            acc[t][3] = fmaf(2.f, acc[t][3], -(sib + sj.y));
        }

        // ---- buffer fully read: release it (before variable-length select)
        __syncwarp();
        if (lane == 0) MBARRIER_ARRIVE(mb_empty + bf * 8);

        // ---- row-max prefilter
        float thrA = finv((uint32_t)(list[ra * KNN + KNN - 1] >> 32));
        float thrB = finv((uint32_t)(list[rb * KNN + KNN - 1] >> 32));
        float mxA = -FLT_MAX, mxB = -FLT_MAX;
        #pragma unroll
        for (int t = 0; t < 8; t++) {
            mxA = fmaxf(mxA, fmaxf(acc[t][0], acc[t][1]));
            mxB = fmaxf(mxB, fmaxf(acc[t][2], acc[t][3]));
        }
        unsigned pend = 0;
        if (mxA >= thrA) pend |= 0x0000FFFFu;
        if (mxB >= thrB) pend |= 0xFFFF0000u;

        // ---- warp-private push / merge rounds (packed u64 keys)
        const int jbase = jt + cbase;
        for (;;) {
            bool ovf = false;
            if (pend & 0x0000FFFFu) {
                float thr = finv((uint32_t)(list[ra * KNN + KNN - 1] >> 32));
                #pragma unroll
                for (int t = 0; t < 8; t++)
                    #pragma unroll
                    for (int v = 0; v < 2; v++) {
                        int bit = t * 2 + v;
                        if ((pend >> bit) & 1u) {
                            float val = acc[t][v];
                            if (val >= thr) {
                                int pos = atomicAdd(&cnt[ra], 1);
                                if (pos < CAP) { cb[ra * CAP + pos] = mkkey(val, jbase + 8 * t + v); pend &= ~(1u << bit); }
                                else ovf = true;
                            } else pend &= ~(1u << bit);
                        }
                    }
            }
            if (pend & 0xFFFF0000u) {
                float thr = finv((uint32_t)(list[rb * KNN + KNN - 1] >> 32));
                #pragma unroll
                for (int t = 0; t < 8; t++)
                    #pragma unroll
                    for (int v = 0; v < 2; v++) {
                        int bit = 16 + t * 2 + v;
                        if ((pend >> bit) & 1u) {
                            float val = acc[t][2 + v];
                            if (val >= thr) {
                                int pos = atomicAdd(&cnt[rb], 1);
                                if (pos < CAP) { cb[rb * CAP + pos] = mkkey(val, jbase + 8 * t + v); pend &= ~(1u << bit); }
                                else ovf = true;
                            } else pend &= ~(1u << bit);
                        }
                    }
            }
            __syncwarp();
            if (lane < 16) {
                int r = rw + lane;
                int m = min(cnt[r], CAP);
                for (int e = 0; e < m; e++) {
                    ull k = cb[r * CAP + e];
                    if (k > list[r * KNN + KNN - 1]) {
                        int p = KNN - 1;
                        while (p > 0) {
                            ull q = list[r * KNN + p - 1];
                            if (k > q) { list[r * KNN + p] = q; p--; }
                            else break;
                        }
                        list[r * KNN + p] = k;
                    }
                }
                cnt[r] = 0;
            }
            bool anyovf = __any_sync(0xFFFFFFFFu, ovf);
            __syncwarp();
            if (!anyovf) break;
        }
    }

    // ---- warp-private output of own rows
    for (int e = lane; e < 16 * KNN; e += 32) {
        int r = rw + e / KNN, k = e % KNN;
        ull key = list[r * KNN + k];
        g_idx[((size_t)b * NPT + i0 + r) * KNN + k] =
            (int)(0xFFFFFFFFu - (uint32_t)(key & 0xFFFFFFFFu));
    }
}

// ---------------- projections u = W1 x, v = (W2 - W1) x ---------------------
#define PROJ_SMEM_WORDS (64*128 + 64*64*2 + 64*64*2)
#define PROJ_SMEM_BYTES (PROJ_SMEM_WORDS * 4)

__global__ __launch_bounds__(256) void k_proj(const float* __restrict__ x,
                                              const float* __restrict__ W) {
    int b = blockIdx.y;
    int n0 = blockIdx.x * 128;
    extern __shared__ float psm[];
    float* xs  = psm;
    ull*   w1d = (ull*)(xs + 64 * 128);
    ull*   wvd = w1d + 64 * 64;
    int tid = threadIdx.x;
    for (int l = tid; l < 64 * 64; l += 256) {
        int o = l >> 6, c = l & 63;
        float a = W[o * 128 + c];
        float bb = W[o * 128 + 64 + c];
        w1d[c * 64 + o] = pack2(a, a);
        wvd[c * 64 + o] = pack2(bb - a, bb - a);
    }
    for (int l = tid; l < 64 * 32; l += 256) {
        int c = l >> 5, nq = l & 31;
        *(float4*)&xs[c * 128 + nq * 4] = *(const float4*)&x[((size_t)b * CH + c) * NPT + n0 + nq * 4];
    }
    __syncthreads();
    int o = tid & 63, ng = tid >> 6;
    for (int pass = 0; pass < 8; pass++) {
        int nl = pass * 16 + ng * 4;
        ull u0 = 0, u1 = 0, v0 = 0, v1 = 0;
        #pragma unroll
        for (int c = 0; c < 64; c++) {
            longlong2 xv = *(const longlong2*)&xs[c * 128 + nl];
            ull w1p = w1d[c * 64 + o];
            ull wvp = wvd[c * 64 + o];
            u0 = ffma2(w1p, (ull)xv.x, u0);
            u1 = ffma2(w1p, (ull)xv.y, u1);
            v0 = ffma2(wvp, (ull)xv.x, v0);
            v1 = ffma2(wvp, (ull)xv.y, v1);
        }
        size_t p = ((size_t)b * NPT + n0 + nl) * OUTC + o;
        float a0, a1;
        unpack2(u0, a0, a1); g_u[p] = a0; g_u[p + OUTC] = a1;
        unpack2(u1, a0, a1); g_u[p + 2 * OUTC] = a0; g_u[p + 3 * OUTC] = a1;
        unpack2(v0, a0, a1); g_v[p] = a0; g_v[p + OUTC] = a1;
        unpack2(v1, a0, a1); g_v[p + 2 * OUTC] = a0; g_v[p + 3 * OUTC] = a1;
    }
}

// ---------------- gather neighbors: umax/umin + fp64 BN stats ---------------
__global__ __launch_bounds__(256) void k_gather() {
    int b = blockIdx.y;
    int base = blockIdx.x * 128;
    int g = threadIdx.x >> 6;
    int o = threadIdx.x & 63;
    const float* ub = g_u + (size_t)b * NPT * OUTC;
    double d1 = 0.0, d2 = 0.0;
    for (int it = 0; it < 32; it++) {
        int i = base + g + (it << 2);
        const int* ip = &g_idx[((size_t)b * NPT + i) * KNN];
        float s1 = 0.f, s2 = 0.f, mx = -FLT_MAX, mn = FLT_MAX;
        #pragma unroll
        for (int k = 0; k < KNN; k++) {
            int j = __ldg(&ip[k]);
            float val = ub[(size_t)j * OUTC + o];
            s1 += val;
            s2 = fmaf(val, val, s2);
            mx = fmaxf(mx, val);
            mn = fminf(mn, val);
        }
        size_t p = ((size_t)b * NPT + i) * OUTC + o;
        float vv = g_v[p];
        g_umax[p] = mx;
        g_umin[p] = mn;
        d1 += (double)s1 + (double)KNN * (double)vv;
        d2 += (double)s2 + 2.0 * (double)vv * (double)s1 + (double)KNN * (double)vv * (double)vv;
    }
    __shared__ double sm1[4][64], sm2[4][64];
    sm1[g][o] = d1;
    sm2[g][o] = d2;
    __syncthreads();
    if (g == 0) {
        double a1 = sm1[0][o] + sm1[1][o] + sm1[2][o] + sm1[3][o];
        double a2 = sm2[0][o] + sm2[1][o] + sm2[2][o] + sm2[3][o];
        atomicAdd(&g_S1[o], a1);
        atomicAdd(&g_S2[o], a2);
    }
}

// ---------------- finalize BN affine ----------------------------------------
__global__ void k_final(const float* __restrict__ gamma, const float* __restrict__ beta) {
    int o = threadIdx.x;
    double M = (double)BATCH * NPT * KNN;
    double mean = g_S1[o] / M;
    double var  = g_S2[o] / M - mean * mean;
    double rs = 1.0 / sqrt(var + 1e-5);
    double a  = (double)gamma[o] * rs;
    double bb = (double)beta[o] - mean * a;
    g_ab[o] = (float)a;
    g_ab[64 + o] = (float)bb;
}

// ---------------- output: affine + LeakyReLU + max-over-k -------------------
__global__ void k_out(float* __restrict__ out) {
    int b = blockIdx.z;
    int n0 = blockIdx.x * 32;
    int o0 = blockIdx.y * 32;
    __shared__ float thi[32][33], tlo[32][33];
    int tx = threadIdx.x, ty = threadIdx.y;
    size_t p = ((size_t)b * NPT + n0 + ty) * OUTC + o0 + tx;
    float v = g_v[p];
    thi[ty][tx] = g_umax[p] + v;
    tlo[ty][tx] = g_umin[p] + v;
    __syncthreads();
    float a  = g_ab[o0 + ty];
    float bb = g_ab[64 + o0 + ty];
    float y = (a >= 0.f) ? thi[tx][ty] : tlo[tx][ty];
    float z = fmaf(a, y, bb);
    out[((size_t)b * OUTC + o0 + ty) * NPT + n0 + tx] = (z >= 0.f) ? z : NEG * z;
}

// ---------------- launcher ---------------------------------------------------
extern "C" void kernel_launch(void* const* d_in, const int* in_sizes, int n_in,
                              void* d_out, int out_size) {
    const float* x     = (const float*)d_in[0];
    const float* W     = (const float*)d_in[1];
    const float* gamma = (const float*)d_in[2];
    const float* beta  = (const float*)d_in[3];
    float* out = (float*)d_out;

    cudaFuncSetAttribute(k_knn,  cudaFuncAttributeMaxDynamicSharedMemorySize, KNN_SMEM_TOTAL);
    cudaFuncSetAttribute(k_proj, cudaFuncAttributeMaxDynamicSharedMemorySize, PROJ_SMEM_BYTES);

    k_init  <<<1, 64>>>();
    k_split <<<dim3(NPT / 256, BATCH), 256>>>(x);
    k_proj  <<<dim3(NPT / 128, BATCH), 256, PROJ_SMEM_BYTES>>>(x, W);
    k_knn   <<<dim3(NPT / TI, BATCH), 256, KNN_SMEM_TOTAL>>>();
    k_gather<<<dim3(NPT / 128, BATCH), 256>>>();
    k_final <<<1, 64>>>(gamma, beta);
    k_out   <<<dim3(NPT / 32, OUTC / 32, BATCH), dim3(32, 32)>>>(out);
}

// round 17
// speedup vs baseline: 1.0277x; 1.0277x over previous
#include <cuda_runtime.h>
#include <cuda_fp16.h>
#include <float.h>
#include <math.h>
#include <cstdint>

#define BATCH 8
#define CH    64
#define NPT   4096
#define OUTC  64
#define KNN   20
#define CK    58          // channels 6..63 used for knn
#define SKIP  6
#define NEG   0.2f
#define KPAD  64          // padded K for MMA

typedef unsigned long long ull;

// ---------------- f32x2 packed math helpers (k_proj) ------------------------
__device__ __forceinline__ ull ffma2(ull a, ull b, ull c) {
    ull d; asm("fma.rn.f32x2 %0, %1, %2, %3;" : "=l"(d) : "l"(a), "l"(b), "l"(c)); return d;
}
__device__ __forceinline__ ull pack2(float lo, float hi) {
    ull r; asm("mov.b64 %0, {%1, %2};" : "=l"(r) : "f"(lo), "f"(hi)); return r;
}
__device__ __forceinline__ void unpack2(ull v, float &lo, float &hi) {
    asm("mov.b64 {%0, %1}, %2;" : "=f"(lo), "=f"(hi) : "l"(v));
}

// ---------------- warp MMA / async helpers (portable sm_80+ PTX) ------------
__device__ __forceinline__ uint32_t smem_u32(const void* p) {
    uint32_t a;
    asm("{ .reg .u64 t; cvta.to.shared.u64 t, %1; cvt.u32.u64 %0, t; }" : "=r"(a) : "l"(p));
    return a;
}
#define LDMX4(d0,d1,d2,d3,addr) \
    asm volatile("ldmatrix.sync.aligned.m8n8.x4.shared.b16 {%0,%1,%2,%3}, [%4];" \
        : "=r"(d0), "=r"(d1), "=r"(d2), "=r"(d3) : "r"(addr))
#define MMA16816(d,a0,a1,a2,a3,b0,b1) \
    asm volatile("mma.sync.aligned.m16n8k16.row.col.f32.f16.f16.f32 " \
        "{%0,%1,%2,%3},{%4,%5,%6,%7},{%8,%9},{%0,%1,%2,%3};" \
        : "+f"((d)[0]), "+f"((d)[1]), "+f"((d)[2]), "+f"((d)[3]) \
        : "r"(a0), "r"(a1), "r"(a2), "r"(a3), "r"(b0), "r"(b1))
#define CPASYNC16(smem_addr, gptr) \
    asm volatile("cp.async.cg.shared.global [%0], [%1], 16;" :: "r"(smem_addr), "l"(gptr))
#define CPASYNC4(smem_addr, gptr) \
    asm volatile("cp.async.ca.shared.global [%0], [%1], 4;" :: "r"(smem_addr), "l"(gptr))
#define CPASYNC_MBAR_ARRIVE(mbar) \
    asm volatile("cp.async.mbarrier.arrive.noinc.shared.b64 [%0];" :: "r"((uint32_t)(mbar)) : "memory")
#define MBARRIER_INIT(mb, c) \
    asm volatile("mbarrier.init.shared.b64 [%0], %1;" :: "r"((uint32_t)(mb)), "r"((uint32_t)(c)) : "memory")
#define MBARRIER_ARRIVE(mb) \
    asm volatile("mbarrier.arrive.shared.b64 _, [%0];" :: "r"((uint32_t)(mb)) : "memory")
#define MBARRIER_WAIT_PARITY(mb, par) do { \
    uint32_t _mb = (uint32_t)(mb), _p = (uint32_t)(par), _done; \
    asm volatile("{\n\t.reg .pred p;\n\t" \
        "mbarrier.try_wait.parity.acquire.cta.shared::cta.b64 p, [%1], %2;\n\t" \
        "selp.b32 %0, 1, 0, p;\n\t}" : "=r"(_done) : "r"(_mb), "r"(_p) : "memory"); \
    if (!_done) { \
        asm volatile("{\n\t.reg .pred P1;\n\t" \
            "WAIT_LOOP_%=:\n\t" \
            "mbarrier.try_wait.parity.acquire.cta.shared::cta.b64 P1, [%0], %1, 0x989680;\n\t" \
            "@P1 bra.uni WAIT_DONE_%=;\n\t" \
            "bra.uni WAIT_LOOP_%=;\n\t" \
            "WAIT_DONE_%=:\n\t}" :: "r"(_mb), "r"(_p) : "memory"); \
    } \
} while (0)

// ---------------- order-preserving float->u32 map ---------------------------
__device__ __forceinline__ uint32_t fmono(float f) {
    uint32_t u = __float_as_uint(f);
    return u ^ ((uint32_t)((int32_t)u >> 31) | 0x80000000u);
}
__device__ __forceinline__ float finv(uint32_t m) {
    uint32_t b = (m & 0x80000000u) ? (m ^ 0x80000000u) : ~m;
    return __uint_as_float(b);
}
__device__ __forceinline__ ull mkkey(float v, int j) {
    return ((ull)fmono(v) << 32) | (ull)(0xFFFFFFFFu - (uint32_t)j);
}

// ---------------- device scratch (static globals: allocation-free) ----------
__device__ unsigned short g_xhi[BATCH*NPT*KPAD];   // fp16 hi, [b][n][k]
__device__ unsigned short g_xlo[BATCH*NPT*KPAD];   // fp16 lo
__device__ float  g_sq  [BATCH*NPT];
__device__ int    g_idx [BATCH*NPT*KNN];
__device__ float  g_u   [BATCH*NPT*OUTC];
__device__ float  g_v   [BATCH*NPT*OUTC];
__device__ float  g_thi [BATCH*NPT*OUTC];   // umax + v
__device__ float  g_tlo [BATCH*NPT*OUTC];   // umin + v
__device__ double g_S1  [OUTC];
__device__ double g_S2  [OUTC];
__device__ float  g_ab  [2*OUTC];

// ---------------- init ------------------------------------------------------
__global__ void k_init() {
    int o = threadIdx.x;
    g_S1[o] = 0.0; g_S2[o] = 0.0;
}

// ---------------- fused: projections + fp16 split + squared norms -----------
// One x read serves: u/v projections, xhi/xlo split tensors, sq norms.
#define PROJ_SMEM_WORDS (64*128 + 64*64*2 + 64*64*2)
#define PROJ_SMEM_BYTES (PROJ_SMEM_WORDS * 4)

__global__ __launch_bounds__(256) void k_proj(const float* __restrict__ x,
                                              const float* __restrict__ W) {
    int b = blockIdx.y;
    int n0 = blockIdx.x * 128;
    extern __shared__ float psm[];
    float* xs  = psm;                       // [64][128] (c-major)
    ull*   w1d = (ull*)(xs + 64 * 128);
    ull*   wvd = w1d + 64 * 64;
    int tid = threadIdx.x;
    for (int l = tid; l < 64 * 64; l += 256) {
        int o = l >> 6, c = l & 63;
        float a = W[o * 128 + c];
        float bb = W[o * 128 + 64 + c];
        w1d[c * 64 + o] = pack2(a, a);
        wvd[c * 64 + o] = pack2(bb - a, bb - a);
    }
    for (int l = tid; l < 64 * 32; l += 256) {
        int c = l >> 5, nq = l & 31;
        *(float4*)&xs[c * 128 + nq * 4] = *(const float4*)&x[((size_t)b * CH + c) * NPT + n0 + nq * 4];
    }
    __syncthreads();

    // ---- split path: each of 128 points handled by 2 threads (k-halves)
    {
        int n = tid >> 1;               // 0..127
        int kh = (tid & 1) * 32;        // k-half base
        size_t ro = ((size_t)b * NPT + n0 + n) * KPAD;
        __half2* xh = (__half2*)(g_xhi + ro);
        __half2* xl = (__half2*)(g_xlo + ro);
        float s = 0.f;
        #pragma unroll
        for (int k2 = 0; k2 < 16; k2++) {
            int k = kh + k2 * 2;
            int c0 = SKIP + k, c1 = SKIP + k + 1;
            float v0 = (c0 < CH) ? xs[c0 * 128 + n] : 0.f;
            float v1 = (c1 < CH) ? xs[c1 * 128 + n] : 0.f;
            s = fmaf(v0, v0, fmaf(v1, v1, s));
            __half h0 = __float2half(v0), h1 = __float2half(v1);
            __half l0 = __float2half(v0 - __half2float(h0));
            __half l1 = __float2half(v1 - __half2float(h1));
            xh[(kh + k2 * 2) >> 1] = __halves2half2(h0, h1);
            xl[(kh + k2 * 2) >> 1] = __halves2half2(l0, l1);
        }
        // sum the two halves via shfl (partner = tid^1)
        float so = __shfl_xor_sync(0xFFFFFFFFu, s, 1);
        if ((tid & 1) == 0) g_sq[b * NPT + n0 + n] = s + so;
    }

    // ---- projection path
    int o = tid & 63, ng = tid >> 6;
    for (int pass = 0; pass < 8; pass++) {
        int nl = pass * 16 + ng * 4;
        ull u0 = 0, u1 = 0, v0 = 0, v1 = 0;
        #pragma unroll
        for (int c = 0; c < 64; c++) {
            longlong2 xv = *(const longlong2*)&xs[c * 128 + nl];
            ull w1p = w1d[c * 64 + o];
            ull wvp = wvd[c * 64 + o];
            u0 = ffma2(w1p, (ull)xv.x, u0);
            u1 = ffma2(w1p, (ull)xv.y, u1);
            v0 = ffma2(wvp, (ull)xv.x, v0);
            v1 = ffma2(wvp, (ull)xv.y, v1);
        }
        size_t p = ((size_t)b * NPT + n0 + nl) * OUTC + o;
        float a0, a1;
        unpack2(u0, a0, a1); g_u[p] = a0; g_u[p + OUTC] = a1;
        unpack2(u1, a0, a1); g_u[p + 2 * OUTC] = a0; g_u[p + 3 * OUTC] = a1;
        unpack2(v0, a0, a1); g_v[p] = a0; g_v[p + OUTC] = a1;
        unpack2(v1, a0, a1); g_v[p + 2 * OUTC] = a0; g_v[p + 3 * OUTC] = a1;
    }
}

// ---------------- fused KNN: HMMA GEMM + mbarrier ring + warp top-20 --------
// (R13 exact version — best measured: 418us)
#define TI 128
#define TJ 64
#define NTILES (NPT / TJ)
#define CAP 16
#define PITCHB 144

#define OFF_B01   36864
#define OFF_SQI   (OFF_B01 + 2 * 18432)
#define OFF_SQJ   (OFF_SQI + TI * 4)
#define OFF_LIST  (OFF_SQJ + 4 * TJ * 4)
#define OFF_CB    (OFF_LIST + TI * KNN * 8)
#define OFF_CNT   (OFF_CB + TI * CAP * 8)
#define OFF_MBAR  (OFF_CNT + TI * 4)
#define KNN_SMEM_TOTAL (OFF_MBAR + 64)

__global__ __launch_bounds__(256, 2) void k_knn() {
    extern __shared__ __align__(16) char smem[];
    const uint32_t sb = smem_u32(smem);
    const int tid = threadIdx.x;
    const int wid = tid >> 5, lane = tid & 31;
    const int b = blockIdx.y;
    const int i0 = blockIdx.x * TI;
    const int d0 = blockIdx.x * 2;

    float* sqi_s = (float*)(smem + OFF_SQI);
    float* sqj_s = (float*)(smem + OFF_SQJ);
    ull*   list  = (ull*)(smem + OFF_LIST);
    ull*   cb    = (ull*)(smem + OFF_CB);
    int*   cnt   = (int*)(smem + OFF_CNT);
    const uint32_t mb_full  = sb + OFF_MBAR;
    const uint32_t mb_empty = sb + OFF_MBAR + 32;

    const uint32_t BUFB[4] = {OFF_B01, OFF_B01 + 18432, 0u, 18432u};

    const int rw = 16 * wid;
    const int ra = rw + (lane >> 2);
    const int rb = ra + 8;

    const int aRow = rw + (lane & 7) + ((lane >> 3) & 1) * 8;
    const int aKB  = ((lane >> 4) & 1) * 16;
    const uint32_t aHI = sb + 0     + aRow * PITCHB + aKB;
    const uint32_t aLO = sb + 18432 + aRow * PITCHB + aKB;
    const int bRow = (lane & 7) + ((lane >> 4) & 1) * 8;
    const int bKB  = ((lane >> 3) & 1) * 16;

    const int pr0 = tid >> 3,         pc0 = tid & 7;
    const int pr1 = (tid + 256) >> 3, pc1 = tid & 7;

    #define TILE_OF(t) ((t) == 0 ? d0 : ((t) == 1 ? d0 + 1 : \
                        (((t) - 2 >= d0) ? (t) : (t) - 2)))

    if (tid == 0) {
        #pragma unroll
        for (int q = 0; q < 4; q++) {
            MBARRIER_INIT(mb_full + q * 8, 256);
            MBARRIER_INIT(mb_empty + q * 8, 8);
        }
    }
    __syncthreads();

    #pragma unroll
    for (int t0 = 0; t0 < 2; t0++) {
        const int jn = TILE_OF(t0) * TJ;
        const uint32_t bh = sb + BUFB[t0];
        CPASYNC16(bh + pr0 * PITCHB + pc0 * 16,
                  g_xhi + ((size_t)b * NPT + jn + pr0) * KPAD + pc0 * 8);
        CPASYNC16(bh + pr1 * PITCHB + pc1 * 16,
                  g_xhi + ((size_t)b * NPT + jn + pr1) * KPAD + pc1 * 8);
        CPASYNC16(bh + 9216 + pr0 * PITCHB + pc0 * 16,
                  g_xlo + ((size_t)b * NPT + jn + pr0) * KPAD + pc0 * 8);
        CPASYNC16(bh + 9216 + pr1 * PITCHB + pc1 * 16,
                  g_xlo + ((size_t)b * NPT + jn + pr1) * KPAD + pc1 * 8);
        if (tid < TJ)
            CPASYNC4(sb + OFF_SQJ + (t0 * TJ + tid) * 4, g_sq + b * NPT + jn + tid);
        CPASYNC_MBAR_ARRIVE(mb_full + t0 * 8);
    }

    const ull WORSTKEY = mkkey(-FLT_MAX, 0x7FFFFFFF);
    for (int l = tid; l < TI * KNN; l += 256) list[l] = WORSTKEY;
    if (tid < TI) { cnt[tid] = 0; sqi_s[tid] = g_sq[b * NPT + i0 + tid]; }
    for (int l = tid; l < TI * 8; l += 256) {
        int r = l >> 3, ch = l & 7;
        *(uint4*)(smem + 0     + r * PITCHB + ch * 16) =
            *(const uint4*)(g_xhi + ((size_t)b * NPT + i0 + r) * KPAD + ch * 8);
        *(uint4*)(smem + 18432 + r * PITCHB + ch * 16) =
            *(const uint4*)(g_xlo + ((size_t)b * NPT + i0 + r) * KPAD + ch * 8);
    }
    __syncthreads();

    uint32_t Ah[4][4], Al[4][4];
    #pragma unroll
    for (int ks = 0; ks < 4; ks++) {
        LDMX4(Ah[ks][0], Ah[ks][1], Ah[ks][2], Ah[ks][3], aHI + ks * 32);
        LDMX4(Al[ks][0], Al[ks][1], Al[ks][2], Al[ks][3], aLO + ks * 32);
    }
    __syncthreads();

    for (int tt = 0; tt < NTILES; tt++) {
        const int bf = tt & 3;
        const int jt = TILE_OF(tt) * TJ;

        const int T2 = tt + 2;
        if (T2 < NTILES) {
            const int b2 = T2 & 3;
            MBARRIER_WAIT_PARITY(mb_empty + b2 * 8, ((T2 >> 2) & 1) ^ 1);
            const int jn = TILE_OF(T2) * TJ;
            const uint32_t bh = sb + BUFB[b2];
            CPASYNC16(bh + pr0 * PITCHB + pc0 * 16,
                      g_xhi + ((size_t)b * NPT + jn + pr0) * KPAD + pc0 * 8);
            CPASYNC16(bh + pr1 * PITCHB + pc1 * 16,
                      g_xhi + ((size_t)b * NPT + jn + pr1) * KPAD + pc1 * 8);
            CPASYNC16(bh + 9216 + pr0 * PITCHB + pc0 * 16,
                      g_xlo + ((size_t)b * NPT + jn + pr0) * KPAD + pc0 * 8);
            CPASYNC16(bh + 9216 + pr1 * PITCHB + pc1 * 16,
                      g_xlo + ((size_t)b * NPT + jn + pr1) * KPAD + pc1 * 8);
            if (tid < TJ)
                CPASYNC4(sb + OFF_SQJ + (b2 * TJ + tid) * 4, g_sq + b * NPT + jn + tid);
            CPASYNC_MBAR_ARRIVE(mb_full + b2 * 8);
        }

        MBARRIER_WAIT_PARITY(mb_full + bf * 8, (tt >> 2) & 1);

        float acc[8][4];
        #pragma unroll
        for (int t = 0; t < 8; t++)
            #pragma unroll
            for (int v = 0; v < 4; v++) acc[t][v] = 0.f;

        const uint32_t bhB = sb + BUFB[bf] + bRow * PITCHB + bKB;
        const uint32_t blB = bhB + 9216;

        #pragma unroll
        for (int ks = 0; ks < 4; ks++) {
            uint32_t bh[4][4];
            #pragma unroll
            for (int p = 0; p < 4; p++)
                LDMX4(bh[p][0], bh[p][1], bh[p][2], bh[p][3],
                      bhB + (16 * p) * PITCHB + ks * 32);
            uint32_t bl0[4], bl1[4];
            LDMX4(bl0[0], bl0[1], bl0[2], bl0[3], blB + ks * 32);
            LDMX4(bl1[0], bl1[1], bl1[2], bl1[3], blB + 16 * PITCHB + ks * 32);
            #pragma unroll
            for (int p = 0; p < 4; p++) {
                MMA16816(acc[2 * p],     Ah[ks][0], Ah[ks][1], Ah[ks][2], Ah[ks][3], bh[p][0], bh[p][1]);
                MMA16816(acc[2 * p + 1], Ah[ks][0], Ah[ks][1], Ah[ks][2], Ah[ks][3], bh[p][2], bh[p][3]);
            }
            #pragma unroll
            for (int p = 0; p < 4; p++) {
                MMA16816(acc[2 * p],     Al[ks][0], Al[ks][1], Al[ks][2], Al[ks][3], bh[p][0], bh[p][1]);
                MMA16816(acc[2 * p + 1], Al[ks][0], Al[ks][1], Al[ks][2], Al[ks][3], bh[p][2], bh[p][3]);
            }
            MMA16816(acc[0], Ah[ks][0], Ah[ks][1], Ah[ks][2], Ah[ks][3], bl0[0], bl0[1]);
            MMA16816(acc[1], Ah[ks][0], Ah[ks][1], Ah[ks][2], Ah[ks][3], bl0[2], bl0[3]);
            MMA16816(acc[2], Ah[ks][0], Ah[ks][1], Ah[ks][2], Ah[ks][3], bl1[0], bl1[1]);
            MMA16816(acc[3], Ah[ks][0], Ah[ks][1], Ah[ks][2], Ah[ks][3], bl1[2], bl1[3]);
            #pragma unroll
            for (int p = 2; p < 4; p++) {
                uint32_t c0, c1, c2, c3;
                LDMX4(c0, c1, c2, c3, blB + (16 * p) * PITCHB + ks * 32);
                MMA16816(acc[2 * p],     Ah[ks][0], Ah[ks][1], Ah[ks][2], Ah[ks][3], c0, c1);
                MMA16816(acc[2 * p + 1], Ah[ks][0], Ah[ks][1], Ah[ks][2], Ah[ks][3], c2, c3);
            }
        }

        const float sia = sqi_s[ra], sib = sqi_s[rb];
        const int cbase = 2 * (lane & 3);
        #pragma unroll
        for (int t = 0; t < 8; t++) {
            float2 sj = *(const float2*)&sqj_s[bf * TJ + 8 * t + cbase];
            acc[t][0] = fmaf(2.f, acc[t][0], -(sia + sj.x));
            acc[t][1] = fmaf(2.f, acc[t][1], -(sia + sj.y));
            acc[t][2] = fmaf(2.f, acc[t][2], -(sib + sj.x));
            acc[t][3] = fmaf(2.f, acc[t][3], -(sib + sj.y));
        }

        __syncwarp();
        if (lane == 0) MBARRIER_ARRIVE(mb_empty + bf * 8);

        float thrA = finv((uint32_t)(list[ra * KNN + KNN - 1] >> 32));
        float thrB = finv((uint32_t)(list[rb * KNN + KNN - 1] >> 32));
        float mxA = -FLT_MAX, mxB = -FLT_MAX;
        #pragma unroll
        for (int t = 0; t < 8; t++) {
            mxA = fmaxf(mxA, fmaxf(acc[t][0], acc[t][1]));
            mxB = fmaxf(mxB, fmaxf(acc[t][2], acc[t][3]));
        }
        unsigned pend = 0;
        if (mxA >= thrA) pend |= 0x0000FFFFu;
        if (mxB >= thrB) pend |= 0xFFFF0000u;

        const int jbase = jt + cbase;
        for (;;) {
            bool ovf = false;
            if (pend & 0x0000FFFFu) {
                float thr = finv((uint32_t)(list[ra * KNN + KNN - 1] >> 32));
                #pragma unroll
                for (int t = 0; t < 8; t++)
                    #pragma unroll
                    for (int v = 0; v < 2; v++) {
                        int bit = t * 2 + v;
                        if ((pend >> bit) & 1u) {
                            float val = acc[t][v];
                            if (val >= thr) {
                                int pos = atomicAdd(&cnt[ra], 1);
                                if (pos < CAP) { cb[ra * CAP + pos] = mkkey(val, jbase + 8 * t + v); pend &= ~(1u << bit); }
                                else ovf = true;
                            } else pend &= ~(1u << bit);
                        }
                    }
            }
            if (pend & 0xFFFF0000u) {
                float thr = finv((uint32_t)(list[rb * KNN + KNN - 1] >> 32));
                #pragma unroll
                for (int t = 0; t < 8; t++)
                    #pragma unroll
                    for (int v = 0; v < 2; v++) {
                        int bit = 16 + t * 2 + v;
                        if ((pend >> bit) & 1u) {
                            float val = acc[t][2 + v];
                            if (val >= thr) {
                                int pos = atomicAdd(&cnt[rb], 1);
                                if (pos < CAP) { cb[rb * CAP + pos] = mkkey(val, jbase + 8 * t + v); pend &= ~(1u << bit); }
                                else ovf = true;
                            } else pend &= ~(1u << bit);
                        }
                    }
            }
            __syncwarp();
            if (lane < 16) {
                int r = rw + lane;
                int m = min(cnt[r], CAP);
                for (int e = 0; e < m; e++) {
                    ull k = cb[r * CAP + e];
                    if (k > list[r * KNN + KNN - 1]) {
                        int p = KNN - 1;
                        while (p > 0) {
                            ull q = list[r * KNN + p - 1];
                            if (k > q) { list[r * KNN + p] = q; p--; }
                            else break;
                        }
                        list[r * KNN + p] = k;
                    }
                }
                cnt[r] = 0;
            }
            bool anyovf = __any_sync(0xFFFFFFFFu, ovf);
            __syncwarp();
            if (!anyovf) break;
        }
    }

    for (int e = lane; e < 16 * KNN; e += 32) {
        int r = rw + e / KNN, k = e % KNN;
        ull key = list[r * KNN + k];
        g_idx[((size_t)b * NPT + i0 + r) * KNN + k] =
            (int)(0xFFFFFFFFu - (uint32_t)(key & 0xFFFFFFFFu));
    }
}

// ---------------- gather: umax/umin + v fold + fp64 BN stats ----------------
__global__ __launch_bounds__(256) void k_gather() {
    int b = blockIdx.y;
    int base = blockIdx.x * 128;
    int g = threadIdx.x >> 6;
    int o = threadIdx.x & 63;
    const float* ub = g_u + (size_t)b * NPT * OUTC;
    double d1 = 0.0, d2 = 0.0;
    for (int it = 0; it < 32; it++) {
        int i = base + g + (it << 2);
        const int* ip = &g_idx[((size_t)b * NPT + i) * KNN];
        float s1 = 0.f, s2 = 0.f, mx = -FLT_MAX, mn = FLT_MAX;
        #pragma unroll
        for (int k = 0; k < KNN; k++) {
            int j = __ldg(&ip[k]);
            float val = ub[(size_t)j * OUTC + o];
            s1 += val;
            s2 = fmaf(val, val, s2);
            mx = fmaxf(mx, val);
            mn = fminf(mn, val);
        }
        size_t p = ((size_t)b * NPT + i) * OUTC + o;
        float vv = g_v[p];
        g_thi[p] = mx + vv;
        g_tlo[p] = mn + vv;
        d1 += (double)s1 + (double)KNN * (double)vv;
        d2 += (double)s2 + 2.0 * (double)vv * (double)s1 + (double)KNN * (double)vv * (double)vv;
    }
    __shared__ double sm1[4][64], sm2[4][64];
    sm1[g][o] = d1;
    sm2[g][o] = d2;
    __syncthreads();
    if (g == 0) {
        double a1 = sm1[0][o] + sm1[1][o] + sm1[2][o] + sm1[3][o];
        double a2 = sm2[0][o] + sm2[1][o] + sm2[2][o] + sm2[3][o];
        atomicAdd(&g_S1[o], a1);
        atomicAdd(&g_S2[o], a2);
    }
}

// ---------------- finalize BN affine ----------------------------------------
__global__ void k_final(const float* __restrict__ gamma, const float* __restrict__ beta) {
    int o = threadIdx.x;
    double M = (double)BATCH * NPT * KNN;
    double mean = g_S1[o] / M;
    double var  = g_S2[o] / M - mean * mean;
    double rs = 1.0 / sqrt(var + 1e-5);
    double a  = (double)gamma[o] * rs;
    double bb = (double)beta[o] - mean * a;
    g_ab[o] = (float)a;
    g_ab[64 + o] = (float)bb;
}

// ---------------- output: affine + LeakyReLU + max-over-k -------------------
__global__ void k_out(float* __restrict__ out) {
    int b = blockIdx.z;
    int n0 = blockIdx.x * 32;
    int o0 = blockIdx.y * 32;
    __shared__ float thi[32][33], tlo[32][33];
    int tx = threadIdx.x, ty = threadIdx.y;
    size_t p = ((size_t)b * NPT + n0 + ty) * OUTC + o0 + tx;
    thi[ty][tx] = g_thi[p];
    tlo[ty][tx] = g_tlo[p];
    __syncthreads();
    float a  = g_ab[o0 + ty];
    float bb = g_ab[64 + o0 + ty];
    float y = (a >= 0.f) ? thi[tx][ty] : tlo[tx][ty];
    float z = fmaf(a, y, bb);
    out[((size_t)b * OUTC + o0 + ty) * NPT + n0 + tx] = (z >= 0.f) ? z : NEG * z;
}

// ---------------- launcher ---------------------------------------------------
extern "C" void kernel_launch(void* const* d_in, const int* in_sizes, int n_in,
                              void* d_out, int out_size) {
    const float* x     = (const float*)d_in[0];
    const float* W     = (const float*)d_in[1];
    const float* gamma = (const float*)d_in[2];
    const float* beta  = (const float*)d_in[3];
    float* out = (float*)d_out;

    cudaFuncSetAttribute(k_knn,  cudaFuncAttributeMaxDynamicSharedMemorySize, KNN_SMEM_TOTAL);
    cudaFuncSetAttribute(k_proj, cudaFuncAttributeMaxDynamicSharedMemorySize, PROJ_SMEM_BYTES);

    k_init  <<<1, 64>>>();
    k_proj  <<<dim3(NPT / 128, BATCH), 256, PROJ_SMEM_BYTES>>>(x, W);
    k_knn   <<<dim3(NPT / TI, BATCH), 256, KNN_SMEM_TOTAL>>>();
    k_gather<<<dim3(NPT / 128, BATCH), 256>>>();
    k_final <<<1, 64>>>(gamma, beta);
    k_out   <<<dim3(NPT / 32, OUTC / 32, BATCH), dim3(32, 32)>>>(out);
}